// round 15
// baseline (speedup 1.0000x reference)
#include <cuda_runtime.h>
#include <cuda_bf16.h>
#include <math.h>

// Problem constants
#define NB 32
#define NU 32
#define NN 1024          // NB*NU utterances
#define TT 128           // max tokens
#define EE 256           // emb dim
#define HH 128           // GRU hidden per dir
#define GG 384           // 3*H gates
#define G2 768           // both directions
#define VSZ 30000

// ---------------- f32x2 helpers (Blackwell packed fp32) ----------------
__device__ __forceinline__ unsigned long long ffma2(unsigned long long a,
                                                    unsigned long long b,
                                                    unsigned long long c)
{
    unsigned long long d;
    asm("fma.rn.f32x2 %0, %1, %2, %3;" : "=l"(d) : "l"(a), "l"(b), "l"(c));
    return d;
}
__device__ __forceinline__ unsigned long long pack2(float lo, float hi)
{
    unsigned long long d;
    asm("mov.b64 %0, {%1, %2};" : "=l"(d) : "f"(lo), "f"(hi));
    return d;
}
__device__ __forceinline__ float2 unpack2(unsigned long long v)
{
    float lo, hi;
    asm("mov.b64 {%0, %1}, %2;" : "=f"(lo), "=f"(hi) : "l"(v));
    return make_float2(lo, hi);
}

// ---------------- scratch (device globals; no cudaMalloc allowed) ----------------
__device__ float g_XP[(size_t)NN * TT * G2];   // input-gate preactivations (f: [0,384), b: [384,768))
__device__ float g_H [(size_t)NN * TT * EE];   // bi-GRU outputs (fwd [0,128), bwd [128,256))
__device__ int   g_lens[NN];
__device__ int   g_order[NN];                  // utterance ids sorted by len (ascending)
__device__ int   g_rows[NN * TT + 128];        // compacted valid (n,t) rows, padded to mult of 128
__device__ int   g_nrows[1];
__device__ float g_wqT[EE * EE];
__device__ float g_wvT[EE * EE];
__device__ float g_woT[EE * EE];
__device__ float g_wlT[EE * EE];

// ---------------- K0: lens, counting sort by len, compacted row list ----------------
__global__ void prep_kernel(const int* __restrict__ d_ids, const int* __restrict__ utt_len)
{
    __shared__ int s_scan[NN];
    __shared__ int hist[129];
    int n = threadIdx.x;                 // 1024 threads
    int b = n >> 5, u = n & 31;
    int l = utt_len[d_ids[b] * NU + u];
    l = min(max(l, 1), TT);
    g_lens[n] = l;

    if (n < 129) hist[n] = 0;
    __syncthreads();
    atomicAdd(&hist[l], 1);
    __syncthreads();
    if (n == 0) {
        int acc = 0;
        for (int i = 1; i <= 128; i++) { int c = hist[i]; hist[i] = acc; acc += c; }
    }
    __syncthreads();
    int pos = atomicAdd(&hist[l], 1);
    g_order[pos] = n;

    // inclusive prefix sum of lens over n (Hillis-Steele)
    s_scan[n] = l;
    __syncthreads();
    for (int off = 1; off < NN; off <<= 1) {
        int v = (n >= off) ? s_scan[n - off] : 0;
        __syncthreads();
        s_scan[n] += v;
        __syncthreads();
    }
    int start = s_scan[n] - l;
    for (int t = 0; t < l; t++) g_rows[start + t] = (n << 7) + t;
    __syncthreads();
    int total  = s_scan[NN - 1];
    int padded = (total + 127) & ~127;
    for (int i = total + n; i < padded; i += NN) g_rows[i] = 0;  // duplicate row 0 (benign)
    if (n == 0) g_nrows[0] = padded;
}

// ---------------- K0b: transpose wq, wv, wo, wl ----------------
__global__ void transpose4_kernel(const float* __restrict__ wq, const float* __restrict__ wv,
                                  const float* __restrict__ wo, const float* __restrict__ wl)
{
    int idx = blockIdx.x * 256 + threadIdx.x;       // 4 * 65536 total
    int m = idx >> 16;
    int r = (idx >> 8) & 255;
    int c = idx & 255;
    const float* src = (m == 0) ? wq : (m == 1) ? wv : (m == 2) ? wo : wl;
    float*       dst = (m == 0) ? g_wqT : (m == 1) ? g_wvT : (m == 2) ? g_woT : g_wlT;
    dst[c * EE + r] = src[r * EE + c];
}

// ---------------- K1: XP = emb[x] @ [w_ih_f; w_ih_b]^T + b_ih  (compacted rows) ----------------
#define BM 128
#define BN 128
#define BK 16
__global__ __launch_bounds__(256) void xp_gemm_kernel(
    const int* __restrict__ x, const float* __restrict__ emb,
    const float* __restrict__ wf, const float* __restrict__ wb,
    const float* __restrict__ bf, const float* __restrict__ bb)
{
    int mt = blockIdx.x;
    int nt = blockIdx.y;
    int nrows = g_nrows[0];
    if (mt * BM >= nrows) return;

    __shared__ __align__(16) float As[BK][BM];      // k-major
    __shared__ __align__(16) float Bs[BK][BN];
    __shared__ int   rowI[BM];
    __shared__ int   tokI[BM];

    int tid = threadIdx.x;
    if (tid < BM) {
        int r = g_rows[mt * BM + tid];
        rowI[tid] = r;
        tokI[tid] = x[r];
    }
    __syncthreads();

    int n0 = nt * BN;  // tile never straddles the 384 boundary (n0 in {0,128,256,384,512,640})
    const float* Wbase    = (n0 < GG) ? (wf + (size_t)n0 * EE) : (wb + (size_t)(n0 - GG) * EE);
    const float* biasBase = (n0 < GG) ? (bf + n0)              : (bb + (n0 - GG));

    unsigned long long acc2[8][4];    // 8 rows x 4 col-pairs, packed f32x2
#pragma unroll
    for (int i = 0; i < 8; i++)
#pragma unroll
        for (int j = 0; j < 4; j++) acc2[i][j] = 0ull;

    int tm = (tid >> 4) << 3;   // row offset (0..120, step 8)
    int tn = (tid & 15) << 3;   // col offset

    for (int k0 = 0; k0 < EE; k0 += BK) {
        // load A: 128 rows x 16 k  (gathered embedding rows)
#pragma unroll
        for (int l = 0; l < 2; l++) {
            int id = tid + l * 256;        // 0..511 float4 slots
            int r  = id >> 2;
            int kq = id & 3;
            float4 v = *(const float4*)(emb + (size_t)tokI[r] * EE + k0 + kq * 4);
            As[kq * 4 + 0][r] = v.x;
            As[kq * 4 + 1][r] = v.y;
            As[kq * 4 + 2][r] = v.z;
            As[kq * 4 + 3][r] = v.w;
        }
        // load B: 16 k x 128 cols (W is gate-major [col][k])
#pragma unroll
        for (int l = 0; l < 2; l++) {
            int id = tid + l * 256;
            int nn = id >> 2;
            int kq = id & 3;
            float4 v = *(const float4*)(Wbase + (size_t)nn * EE + k0 + kq * 4);
            Bs[kq * 4 + 0][nn] = v.x;
            Bs[kq * 4 + 1][nn] = v.y;
            Bs[kq * 4 + 2][nn] = v.z;
            Bs[kq * 4 + 3][nn] = v.w;
        }
        __syncthreads();
#pragma unroll
        for (int k = 0; k < BK; k++) {
            float4 a0 = *(const float4*)&As[k][tm];
            float4 a1 = *(const float4*)&As[k][tm + 4];
            ulonglong2 b0 = *(const ulonglong2*)&Bs[k][tn];      // col pairs 0,1
            ulonglong2 b1 = *(const ulonglong2*)&Bs[k][tn + 4];  // col pairs 2,3
            unsigned long long bn2[4] = {b0.x, b0.y, b1.x, b1.y};
            float am[8] = {a0.x, a0.y, a0.z, a0.w, a1.x, a1.y, a1.z, a1.w};
#pragma unroll
            for (int i = 0; i < 8; i++) {
                unsigned long long ad = pack2(am[i], am[i]);
#pragma unroll
                for (int j = 0; j < 4; j++) acc2[i][j] = ffma2(ad, bn2[j], acc2[i][j]);
            }
        }
        __syncthreads();
    }

    // epilogue: add bias, write to XP
    float bias[8];
#pragma unroll
    for (int j = 0; j < 8; j++) bias[j] = biasBase[tn + j];
#pragma unroll
    for (int i = 0; i < 8; i++) {
        int row = rowI[tm + i];
        float* dst = g_XP + (size_t)row * G2 + n0 + tn;
        float2 p0 = unpack2(acc2[i][0]);
        float2 p1 = unpack2(acc2[i][1]);
        float2 p2 = unpack2(acc2[i][2]);
        float2 p3 = unpack2(acc2[i][3]);
        float4 v0, v1;
        v0.x = p0.x + bias[0]; v0.y = p0.y + bias[1];
        v0.z = p1.x + bias[2]; v0.w = p1.y + bias[3];
        v1.x = p2.x + bias[4]; v1.y = p2.y + bias[5];
        v1.z = p3.x + bias[6]; v1.w = p3.y + bias[7];
        *(float4*)(dst)     = v0;
        *(float4*)(dst + 4) = v1;
    }
}

// ---------------- K2: persistent GRU recurrence (packed f32x2 weights in registers) ----------------
// grid: 512 blocks = 2 dirs x 256 blocks; each block = 4 utterances; 384 threads = 1/gate
#define RROWS 4
__global__ __launch_bounds__(384, 1) void gru_kernel(
    const float* __restrict__ whh_f, const float* __restrict__ bhh_f,
    const float* __restrict__ whh_b, const float* __restrict__ bhh_b)
{
    int dir = blockIdx.x >> 8;          // 0 fwd, 1 bwd
    int blk = blockIdx.x & 255;
    const float* whh = dir ? whh_b : whh_f;
    const float* bhh = dir ? bhh_b : bhh_f;
    int g = threadIdx.x;                // gate id 0..383

    // weight row packed into f32x2 registers (64 u64 = 128 regs)
    unsigned long long w2[HH / 2];
#pragma unroll
    for (int j = 0; j < HH / 4; j++) {
        float4 t = *(const float4*)(whh + (size_t)g * HH + 4 * j);
        w2[2 * j]     = pack2(t.x, t.y);
        w2[2 * j + 1] = pack2(t.z, t.w);
    }
    float bh = bhh[g];

    __shared__ __align__(16) float hsh[RROWS][HH];
    __shared__ float  gh[RROWS][GG];
    __shared__ float  xs[RROWS][GG];
    __shared__ int    s_rown[RROWS], s_rlen[RROWS], s_ml;

    if (g < RROWS) {
        int n = g_order[blk * RROWS + g];
        s_rown[g] = n;
        s_rlen[g] = g_lens[n];
    }
    if (g < HH) {
#pragma unroll
        for (int r = 0; r < RROWS; r++) hsh[r][g] = 0.f;
    }
    if (g == 0) {
        int m = 0;
        // lens sorted ascending within the block -> last is max, but be safe
        s_ml = 0;
    }
    __syncthreads();
    if (g == 0) {
        int m = 0;
#pragma unroll
        for (int r = 0; r < RROWS; r++) m = max(m, s_rlen[r]);
        s_ml = m;
    }
    __syncthreads();

    int ml = s_ml;
    int dcol = dir ? GG : 0;

    for (int s = 0; s < ml; s++) {
        // issue XP loads (latency hidden behind the dot)
        float xv[RROWS];
#pragma unroll
        for (int r = 0; r < RROWS; r++) {
            int p = dir ? (s_rlen[r] - 1 - s) : s;
            p = min(max(p, 0), TT - 1);
            xv[r] = g_XP[(size_t)((s_rown[r] << 7) + p) * G2 + dcol + g];
        }
        // recurrent dot: acc[r] = b_hh[g] + w_hh[g,:] . h[r,:]  (packed f32x2)
        unsigned long long acc2[RROWS];
#pragma unroll
        for (int r = 0; r < RROWS; r++) acc2[r] = 0ull;
#pragma unroll
        for (int kk = 0; kk < HH / 4; kk++) {
#pragma unroll
            for (int r = 0; r < RROWS; r++) {
                ulonglong2 hv = ((const ulonglong2*)hsh[r])[kk];
                acc2[r] = ffma2(w2[2 * kk],     hv.x, acc2[r]);
                acc2[r] = ffma2(w2[2 * kk + 1], hv.y, acc2[r]);
            }
        }
#pragma unroll
        for (int r = 0; r < RROWS; r++) {
            float2 f = unpack2(acc2[r]);
            gh[r][g] = bh + f.x + f.y;
            xs[r][g] = xv[r];
        }
        __syncthreads();

        if (g < HH) {
#pragma unroll
            for (int r = 0; r < RROWS; r++) {
                if (s < s_rlen[r]) {
                    float pr = xs[r][g]      + gh[r][g];
                    float pz = xs[r][g + HH] + gh[r][g + HH];
                    // fast sigmoid via HW EX2 + approx rcp (~1e-6 rel err, tol is 1e-3)
                    float rr = __fdividef(1.f, 1.f + __expf(-pr));
                    float zz = __fdividef(1.f, 1.f + __expf(-pz));
                    float pn = xs[r][g + 2 * HH] + rr * gh[r][g + 2 * HH];
                    // tanh(x) = 2/(1+exp(-2x)) - 1
                    float nn = __fdividef(2.f, 1.f + __expf(-2.f * pn)) - 1.f;
                    float hp = hsh[r][g];
                    float hn = (1.f - zz) * nn + zz * hp;
                    hsh[r][g] = hn;
                    int p = dir ? (s_rlen[r] - 1 - s) : s;  // original time position
                    g_H[(size_t)((s_rown[r] << 7) + p) * EE + dir * HH + g] = hn;
                }
            }
        }
        __syncthreads();
    }
}

// ---------------- K3: attention pooling + output linears (algebraically fused) ----------------
__global__ __launch_bounds__(256) void attn_kernel(
    const float* __restrict__ bq, const float* __restrict__ wk, const float* __restrict__ bk,
    const float* __restrict__ bv, const float* __restrict__ bo, const float* __restrict__ bl,
    float* __restrict__ out)
{
    int n = blockIdx.x;
    int e = threadIdx.x;     // 256 threads
    __shared__ float hl[EE];       // reused buffer A
    __shared__ float qs[EE];       // reused buffer B
    __shared__ float qks[EE];
    __shared__ float sc[TT];
    __shared__ float vb[EE];
    __shared__ float red[8];

    int len = g_lens[n];
    const float* Hn = g_H + (size_t)n * TT * EE;

    hl[e] = Hn[(size_t)(len - 1) * EE + e];
    __syncthreads();

    // q = wq @ h_last + bq    (wqT[k][e])
    float a = bq[e];
#pragma unroll 4
    for (int k = 0; k < EE; k++) a += g_wqT[k * EE + e] * hl[k];
    qs[e] = a;
    __syncthreads();

    // qb = q . bk   (block reduce)
    float p = qs[e] * bk[e];
#pragma unroll
    for (int o = 16; o > 0; o >>= 1) p += __shfl_xor_sync(0xffffffffu, p, o);
    if ((e & 31) == 0) red[e >> 5] = p;
    __syncthreads();
    float qb = 0.f;
#pragma unroll
    for (int i = 0; i < 8; i++) qb += red[i];
    __syncthreads();

    // qk[e] = sum_j q[j] * wk[j][e]
    float b2 = 0.f;
#pragma unroll 4
    for (int j = 0; j < EE; j++) b2 += qs[j] * wk[j * EE + e];
    qks[e] = b2;
    __syncthreads();

    // scores (one thread per t)
    if (e < TT && e < len) {
        const float4* hrow = (const float4*)(Hn + (size_t)e * EE);
        const float4* qk4  = (const float4*)qks;
        float s = qb;
#pragma unroll 8
        for (int k = 0; k < EE / 4; k++) {
            float4 hv = hrow[k];
            float4 qv = qk4[k];
            s += hv.x * qv.x + hv.y * qv.y + hv.z * qv.z + hv.w * qv.w;
        }
        sc[e] = s * (1.0f / 16.0f);   // SCALE = sqrt(256)
    }
    __syncthreads();

    // softmax over t < len
    float m = -INFINITY;
    if (e < len) m = sc[e];
#pragma unroll
    for (int o = 16; o > 0; o >>= 1) m = fmaxf(m, __shfl_xor_sync(0xffffffffu, m, o));
    if ((e & 31) == 0) red[e >> 5] = m;
    __syncthreads();
    float M = -INFINITY;
#pragma unroll
    for (int i = 0; i < 8; i++) M = fmaxf(M, red[i]);
    __syncthreads();

    float ssum = 0.f;
    if (e < len) {
        float ex = expf(sc[e] - M);
        sc[e] = ex;
        ssum = ex;
    }
#pragma unroll
    for (int o = 16; o > 0; o >>= 1) ssum += __shfl_xor_sync(0xffffffffu, ssum, o);
    if ((e & 31) == 0) red[e >> 5] = ssum;
    __syncthreads();
    float S = 0.f;
#pragma unroll
    for (int i = 0; i < 8; i++) S += red[i];
    float invS = 1.0f / S;
    __syncthreads();

    // hbar[e] = sum_t attn[t] * H[t][e]
    float hb = 0.f;
    for (int t = 0; t < len; t++) hb += sc[t] * Hn[(size_t)t * EE + e];
    hb *= invS;
    vb[e] = hb;
    __syncthreads();

    // ctx = wv @ hbar + bv
    float c = bv[e];
#pragma unroll 4
    for (int k = 0; k < EE; k++) c += g_wvT[k * EE + e] * vb[k];
    hl[e] = c;
    __syncthreads();

    // o1 = wo @ ctx + bo
    float o1 = bo[e];
#pragma unroll 4
    for (int k = 0; k < EE; k++) o1 += g_woT[k * EE + e] * hl[k];
    qs[e] = o1;
    __syncthreads();

    // out = wl @ o1 + bl
    float f = bl[e];
#pragma unroll 4
    for (int k = 0; k < EE; k++) f += g_wlT[k * EE + e] * qs[k];
    out[(size_t)n * EE + e] = f;
}

// ---------------- launch ----------------
extern "C" void kernel_launch(void* const* d_in, const int* in_sizes, int n_in,
                              void* d_out, int out_size)
{
    const int*   x       = (const int*)  d_in[0];
    const int*   d_ids   = (const int*)  d_in[1];
    const int*   utt_len = (const int*)  d_in[2];
    const float* emb     = (const float*)d_in[3];
    const float* w_ih_f  = (const float*)d_in[4];
    const float* w_hh_f  = (const float*)d_in[5];
    const float* b_ih_f  = (const float*)d_in[6];
    const float* b_hh_f  = (const float*)d_in[7];
    const float* w_ih_b  = (const float*)d_in[8];
    const float* w_hh_b  = (const float*)d_in[9];
    const float* b_ih_b  = (const float*)d_in[10];
    const float* b_hh_b  = (const float*)d_in[11];
    const float* wq      = (const float*)d_in[12];
    const float* bq      = (const float*)d_in[13];
    const float* wk      = (const float*)d_in[14];
    const float* bk      = (const float*)d_in[15];
    const float* wv      = (const float*)d_in[16];
    const float* bv      = (const float*)d_in[17];
    const float* wo      = (const float*)d_in[18];
    const float* bo      = (const float*)d_in[19];
    const float* wl      = (const float*)d_in[20];
    const float* bl      = (const float*)d_in[21];
    float* out = (float*)d_out;

    prep_kernel<<<1, 1024>>>(d_ids, utt_len);
    transpose4_kernel<<<(4 * EE * EE) / 256, 256>>>(wq, wv, wo, wl);
    dim3 g1(NN * TT / BM, G2 / BN);
    xp_gemm_kernel<<<g1, 256>>>(x, emb, w_ih_f, w_ih_b, b_ih_f, b_ih_b);
    gru_kernel<<<512, 384>>>(w_hh_f, b_hh_f, w_hh_b, b_hh_b);
    attn_kernel<<<NN, 256>>>(bq, wk, bk, bv, bo, bl, out);
}

// round 16
// speedup vs baseline: 1.0097x; 1.0097x over previous
#include <cuda_runtime.h>
#include <cuda_bf16.h>
#include <math.h>

// Problem constants
#define NB 32
#define NU 32
#define NN 1024          // NB*NU utterances
#define TT 128           // max tokens
#define EE 256           // emb dim
#define HH 128           // GRU hidden per dir
#define GG 384           // 3*H gates
#define G2 768           // both directions
#define VSZ 30000

// ---------------- f32x2 helpers (Blackwell packed fp32) ----------------
__device__ __forceinline__ unsigned long long ffma2(unsigned long long a,
                                                    unsigned long long b,
                                                    unsigned long long c)
{
    unsigned long long d;
    asm("fma.rn.f32x2 %0, %1, %2, %3;" : "=l"(d) : "l"(a), "l"(b), "l"(c));
    return d;
}
__device__ __forceinline__ unsigned long long pack2(float lo, float hi)
{
    unsigned long long d;
    asm("mov.b64 %0, {%1, %2};" : "=l"(d) : "f"(lo), "f"(hi));
    return d;
}
__device__ __forceinline__ float2 unpack2(unsigned long long v)
{
    float lo, hi;
    asm("mov.b64 {%0, %1}, %2;" : "=f"(lo), "=f"(hi) : "l"(v));
    return make_float2(lo, hi);
}

// ---------------- scratch (device globals; no cudaMalloc allowed) ----------------
__device__ float g_XP[(size_t)NN * TT * G2];   // input-gate preactivations (f: [0,384), b: [384,768))
__device__ float g_H [(size_t)NN * TT * EE];   // bi-GRU outputs (fwd [0,128), bwd [128,256))
__device__ int   g_lens[NN];
__device__ int   g_order[NN];                  // utterance ids sorted by len (ascending)
__device__ int   g_rows[NN * TT + 128];        // compacted valid (n,t) rows, padded to mult of 128
__device__ int   g_nrows[1];
__device__ float g_wqT[EE * EE];
__device__ float g_wvT[EE * EE];
__device__ float g_woT[EE * EE];
__device__ float g_wlT[EE * EE];

// ---------------- K0: lens, counting sort by len, compacted row list ----------------
__global__ void prep_kernel(const int* __restrict__ d_ids, const int* __restrict__ utt_len)
{
    __shared__ int s_scan[NN];
    __shared__ int hist[129];
    int n = threadIdx.x;                 // 1024 threads
    int b = n >> 5, u = n & 31;
    int l = utt_len[d_ids[b] * NU + u];
    l = min(max(l, 1), TT);
    g_lens[n] = l;

    if (n < 129) hist[n] = 0;
    __syncthreads();
    atomicAdd(&hist[l], 1);
    __syncthreads();
    if (n == 0) {
        int acc = 0;
        for (int i = 1; i <= 128; i++) { int c = hist[i]; hist[i] = acc; acc += c; }
    }
    __syncthreads();
    int pos = atomicAdd(&hist[l], 1);
    g_order[pos] = n;

    // inclusive prefix sum of lens over n (Hillis-Steele)
    s_scan[n] = l;
    __syncthreads();
    for (int off = 1; off < NN; off <<= 1) {
        int v = (n >= off) ? s_scan[n - off] : 0;
        __syncthreads();
        s_scan[n] += v;
        __syncthreads();
    }
    int start = s_scan[n] - l;
    for (int t = 0; t < l; t++) g_rows[start + t] = (n << 7) + t;
    __syncthreads();
    int total  = s_scan[NN - 1];
    int padded = (total + 127) & ~127;
    for (int i = total + n; i < padded; i += NN) g_rows[i] = 0;  // duplicate row 0 (benign)
    if (n == 0) g_nrows[0] = padded;
}

// ---------------- K0b: transpose wq, wv, wo, wl ----------------
__global__ void transpose4_kernel(const float* __restrict__ wq, const float* __restrict__ wv,
                                  const float* __restrict__ wo, const float* __restrict__ wl)
{
    int idx = blockIdx.x * 256 + threadIdx.x;       // 4 * 65536 total
    int m = idx >> 16;
    int r = (idx >> 8) & 255;
    int c = idx & 255;
    const float* src = (m == 0) ? wq : (m == 1) ? wv : (m == 2) ? wo : wl;
    float*       dst = (m == 0) ? g_wqT : (m == 1) ? g_wvT : (m == 2) ? g_woT : g_wlT;
    dst[c * EE + r] = src[r * EE + c];
}

// ---------------- K1: XP = emb[x] @ [w_ih_f; w_ih_b]^T + b_ih  (compacted rows) ----------------
#define BM 128
#define BN 128
#define BK 16
__global__ __launch_bounds__(256) void xp_gemm_kernel(
    const int* __restrict__ x, const float* __restrict__ emb,
    const float* __restrict__ wf, const float* __restrict__ wb,
    const float* __restrict__ bf, const float* __restrict__ bb)
{
    int mt = blockIdx.x;
    int nt = blockIdx.y;
    int nrows = g_nrows[0];
    if (mt * BM >= nrows) return;

    __shared__ __align__(16) float As[BK][BM];      // k-major
    __shared__ __align__(16) float Bs[BK][BN];
    __shared__ int   rowI[BM];
    __shared__ int   tokI[BM];

    int tid = threadIdx.x;
    if (tid < BM) {
        int r = g_rows[mt * BM + tid];
        rowI[tid] = r;
        tokI[tid] = x[r];
    }
    __syncthreads();

    int n0 = nt * BN;  // tile never straddles the 384 boundary (n0 in {0,128,256,384,512,640})
    const float* Wbase    = (n0 < GG) ? (wf + (size_t)n0 * EE) : (wb + (size_t)(n0 - GG) * EE);
    const float* biasBase = (n0 < GG) ? (bf + n0)              : (bb + (n0 - GG));

    unsigned long long acc2[8][4];    // 8 rows x 4 col-pairs, packed f32x2
#pragma unroll
    for (int i = 0; i < 8; i++)
#pragma unroll
        for (int j = 0; j < 4; j++) acc2[i][j] = 0ull;

    int tm = (tid >> 4) << 3;   // row offset (0..120, step 8)
    int tn = (tid & 15) << 3;   // col offset

    for (int k0 = 0; k0 < EE; k0 += BK) {
        // load A: 128 rows x 16 k  (gathered embedding rows)
#pragma unroll
        for (int l = 0; l < 2; l++) {
            int id = tid + l * 256;        // 0..511 float4 slots
            int r  = id >> 2;
            int kq = id & 3;
            float4 v = *(const float4*)(emb + (size_t)tokI[r] * EE + k0 + kq * 4);
            As[kq * 4 + 0][r] = v.x;
            As[kq * 4 + 1][r] = v.y;
            As[kq * 4 + 2][r] = v.z;
            As[kq * 4 + 3][r] = v.w;
        }
        // load B: 16 k x 128 cols (W is gate-major [col][k])
#pragma unroll
        for (int l = 0; l < 2; l++) {
            int id = tid + l * 256;
            int nn = id >> 2;
            int kq = id & 3;
            float4 v = *(const float4*)(Wbase + (size_t)nn * EE + k0 + kq * 4);
            Bs[kq * 4 + 0][nn] = v.x;
            Bs[kq * 4 + 1][nn] = v.y;
            Bs[kq * 4 + 2][nn] = v.z;
            Bs[kq * 4 + 3][nn] = v.w;
        }
        __syncthreads();
#pragma unroll
        for (int k = 0; k < BK; k++) {
            float4 a0 = *(const float4*)&As[k][tm];
            float4 a1 = *(const float4*)&As[k][tm + 4];
            ulonglong2 b0 = *(const ulonglong2*)&Bs[k][tn];      // col pairs 0,1
            ulonglong2 b1 = *(const ulonglong2*)&Bs[k][tn + 4];  // col pairs 2,3
            unsigned long long bn2[4] = {b0.x, b0.y, b1.x, b1.y};
            float am[8] = {a0.x, a0.y, a0.z, a0.w, a1.x, a1.y, a1.z, a1.w};
#pragma unroll
            for (int i = 0; i < 8; i++) {
                unsigned long long ad = pack2(am[i], am[i]);
#pragma unroll
                for (int j = 0; j < 4; j++) acc2[i][j] = ffma2(ad, bn2[j], acc2[i][j]);
            }
        }
        __syncthreads();
    }

    // epilogue: add bias, write to XP
    float bias[8];
#pragma unroll
    for (int j = 0; j < 8; j++) bias[j] = biasBase[tn + j];
#pragma unroll
    for (int i = 0; i < 8; i++) {
        int row = rowI[tm + i];
        float* dst = g_XP + (size_t)row * G2 + n0 + tn;
        float2 p0 = unpack2(acc2[i][0]);
        float2 p1 = unpack2(acc2[i][1]);
        float2 p2 = unpack2(acc2[i][2]);
        float2 p3 = unpack2(acc2[i][3]);
        float4 v0, v1;
        v0.x = p0.x + bias[0]; v0.y = p0.y + bias[1];
        v0.z = p1.x + bias[2]; v0.w = p1.y + bias[3];
        v1.x = p2.x + bias[4]; v1.y = p2.y + bias[5];
        v1.z = p3.x + bias[6]; v1.w = p3.y + bias[7];
        *(float4*)(dst)     = v0;
        *(float4*)(dst + 4) = v1;
    }
}

// ---------------- K2: persistent GRU recurrence, 2-way k-split over 768 threads ----------------
// grid: 512 blocks = 2 dirs x 256 blocks; each block = 4 utterances.
// Thread t: half = t/384 (k range [half*64, half*64+64)), g = t%384 (gate id).
// Each thread holds half a weight row (32 u64 = 64 regs) -> fits 85-reg budget at 768 thr.
#define RROWS 4
#define KH (HH / 2)      // 64 k per half
__global__ __launch_bounds__(768, 1) void gru_kernel(
    const float* __restrict__ whh_f, const float* __restrict__ bhh_f,
    const float* __restrict__ whh_b, const float* __restrict__ bhh_b)
{
    int dir = blockIdx.x >> 8;          // 0 fwd, 1 bwd
    int blk = blockIdx.x & 255;
    const float* whh = dir ? whh_b : whh_f;
    const float* bhh = dir ? bhh_b : bhh_f;
    int t = threadIdx.x;                // 0..767
    int half = (t >= 384) ? 1 : 0;
    int g = t - half * 384;             // gate id 0..383
    int koff = half * KH;               // k offset for this half

    // half weight row packed into f32x2 registers (32 u64 = 64 regs)
    unsigned long long w2[KH / 2];
#pragma unroll
    for (int j = 0; j < KH / 4; j++) {
        float4 v = *(const float4*)(whh + (size_t)g * HH + koff + 4 * j);
        w2[2 * j]     = pack2(v.x, v.y);
        w2[2 * j + 1] = pack2(v.z, v.w);
    }
    float bh = (half == 0) ? bhh[g] : 0.f;   // fold bias into half-0 partial

    __shared__ __align__(16) float hsh[RROWS][HH];
    __shared__ float  part[RROWS][2 * GG];   // partial dots, indexed by t
    __shared__ float  xs[RROWS][GG];
    __shared__ int    s_rown[RROWS], s_rlen[RROWS], s_ml;

    if (t < RROWS) {
        int n = g_order[blk * RROWS + t];
        s_rown[t] = n;
        s_rlen[t] = g_lens[n];
    }
    if (t < HH) {
#pragma unroll
        for (int r = 0; r < RROWS; r++) hsh[r][t] = 0.f;
    }
    __syncthreads();
    if (t == 0) {
        int m = 0;
#pragma unroll
        for (int r = 0; r < RROWS; r++) m = max(m, s_rlen[r]);
        s_ml = m;
    }
    __syncthreads();

    int ml = s_ml;
    int dcol = dir ? GG : 0;

    for (int s = 0; s < ml; s++) {
        // half-0 threads fetch x preactivations (latency hidden behind the dot)
        float xv[RROWS];
        if (half == 0) {
#pragma unroll
            for (int r = 0; r < RROWS; r++) {
                int p = dir ? (s_rlen[r] - 1 - s) : s;
                p = min(max(p, 0), TT - 1);
                xv[r] = g_XP[(size_t)((s_rown[r] << 7) + p) * G2 + dcol + g];
            }
        }

        // partial recurrent dot over this half's 64 h values (packed f32x2)
        unsigned long long acc2[RROWS];
#pragma unroll
        for (int r = 0; r < RROWS; r++) acc2[r] = 0ull;
#pragma unroll
        for (int kk = 0; kk < KH / 4; kk++) {
#pragma unroll
            for (int r = 0; r < RROWS; r++) {
                ulonglong2 hv = ((const ulonglong2*)(hsh[r] + koff))[kk];
                acc2[r] = ffma2(w2[2 * kk],     hv.x, acc2[r]);
                acc2[r] = ffma2(w2[2 * kk + 1], hv.y, acc2[r]);
            }
        }
#pragma unroll
        for (int r = 0; r < RROWS; r++) {
            float2 f = unpack2(acc2[r]);
            part[r][t] = bh + f.x + f.y;
        }
        if (half == 0) {
#pragma unroll
            for (int r = 0; r < RROWS; r++) xs[r][g] = xv[r];
        }
        __syncthreads();

        // activation: 8 warps (g<128 in both halves); half 0 -> rows 0,1; half 1 -> rows 2,3
        if (g < HH) {
#pragma unroll
            for (int rr2 = 0; rr2 < 2; rr2++) {
                int r = half * 2 + rr2;
                int rl = s_rlen[r];
                if (s < rl) {
                    float d0 = part[r][g]          + part[r][g + GG];
                    float d1 = part[r][g + HH]     + part[r][g + HH + GG];
                    float d2 = part[r][g + 2 * HH] + part[r][g + 2 * HH + GG];
                    float pr = xs[r][g]          + d0;
                    float pz = xs[r][g + HH]     + d1;
                    float rr = __fdividef(1.f, 1.f + __expf(-pr));
                    float zz = __fdividef(1.f, 1.f + __expf(-pz));
                    float pn = xs[r][g + 2 * HH] + rr * d2;
                    float nn = __fdividef(2.f, 1.f + __expf(-2.f * pn)) - 1.f;
                    float hp = hsh[r][g];
                    float hn = (1.f - zz) * nn + zz * hp;
                    hsh[r][g] = hn;
                    int p = dir ? (rl - 1 - s) : s;  // original time position
                    g_H[(size_t)((s_rown[r] << 7) + p) * EE + dir * HH + g] = hn;
                }
            }
        }
        __syncthreads();
    }
}

// ---------------- K3: attention pooling + output linears (algebraically fused) ----------------
__global__ __launch_bounds__(256) void attn_kernel(
    const float* __restrict__ bq, const float* __restrict__ wk, const float* __restrict__ bk,
    const float* __restrict__ bv, const float* __restrict__ bo, const float* __restrict__ bl,
    float* __restrict__ out)
{
    int n = blockIdx.x;
    int e = threadIdx.x;     // 256 threads
    __shared__ float hl[EE];       // reused buffer A
    __shared__ float qs[EE];       // reused buffer B
    __shared__ float qks[EE];
    __shared__ float sc[TT];
    __shared__ float vb[EE];
    __shared__ float red[8];

    int len = g_lens[n];
    const float* Hn = g_H + (size_t)n * TT * EE;

    hl[e] = Hn[(size_t)(len - 1) * EE + e];
    __syncthreads();

    // q = wq @ h_last + bq    (wqT[k][e])
    float a = bq[e];
#pragma unroll 4
    for (int k = 0; k < EE; k++) a += g_wqT[k * EE + e] * hl[k];
    qs[e] = a;
    __syncthreads();

    // qb = q . bk   (block reduce)
    float p = qs[e] * bk[e];
#pragma unroll
    for (int o = 16; o > 0; o >>= 1) p += __shfl_xor_sync(0xffffffffu, p, o);
    if ((e & 31) == 0) red[e >> 5] = p;
    __syncthreads();
    float qb = 0.f;
#pragma unroll
    for (int i = 0; i < 8; i++) qb += red[i];
    __syncthreads();

    // qk[e] = sum_j q[j] * wk[j][e]
    float b2 = 0.f;
#pragma unroll 4
    for (int j = 0; j < EE; j++) b2 += qs[j] * wk[j * EE + e];
    qks[e] = b2;
    __syncthreads();

    // scores (one thread per t)
    if (e < TT && e < len) {
        const float4* hrow = (const float4*)(Hn + (size_t)e * EE);
        const float4* qk4  = (const float4*)qks;
        float s = qb;
#pragma unroll 8
        for (int k = 0; k < EE / 4; k++) {
            float4 hv = hrow[k];
            float4 qv = qk4[k];
            s += hv.x * qv.x + hv.y * qv.y + hv.z * qv.z + hv.w * qv.w;
        }
        sc[e] = s * (1.0f / 16.0f);   // SCALE = sqrt(256)
    }
    __syncthreads();

    // softmax over t < len
    float m = -INFINITY;
    if (e < len) m = sc[e];
#pragma unroll
    for (int o = 16; o > 0; o >>= 1) m = fmaxf(m, __shfl_xor_sync(0xffffffffu, m, o));
    if ((e & 31) == 0) red[e >> 5] = m;
    __syncthreads();
    float M = -INFINITY;
#pragma unroll
    for (int i = 0; i < 8; i++) M = fmaxf(M, red[i]);
    __syncthreads();

    float ssum = 0.f;
    if (e < len) {
        float ex = expf(sc[e] - M);
        sc[e] = ex;
        ssum = ex;
    }
#pragma unroll
    for (int o = 16; o > 0; o >>= 1) ssum += __shfl_xor_sync(0xffffffffu, ssum, o);
    if ((e & 31) == 0) red[e >> 5] = ssum;
    __syncthreads();
    float S = 0.f;
#pragma unroll
    for (int i = 0; i < 8; i++) S += red[i];
    float invS = 1.0f / S;
    __syncthreads();

    // hbar[e] = sum_t attn[t] * H[t][e]
    float hb = 0.f;
    for (int t = 0; t < len; t++) hb += sc[t] * Hn[(size_t)t * EE + e];
    hb *= invS;
    vb[e] = hb;
    __syncthreads();

    // ctx = wv @ hbar + bv
    float c = bv[e];
#pragma unroll 4
    for (int k = 0; k < EE; k++) c += g_wvT[k * EE + e] * vb[k];
    hl[e] = c;
    __syncthreads();

    // o1 = wo @ ctx + bo
    float o1 = bo[e];
#pragma unroll 4
    for (int k = 0; k < EE; k++) o1 += g_woT[k * EE + e] * hl[k];
    qs[e] = o1;
    __syncthreads();

    // out = wl @ o1 + bl
    float f = bl[e];
#pragma unroll 4
    for (int k = 0; k < EE; k++) f += g_wlT[k * EE + e] * qs[k];
    out[(size_t)n * EE + e] = f;
}

// ---------------- launch ----------------
extern "C" void kernel_launch(void* const* d_in, const int* in_sizes, int n_in,
                              void* d_out, int out_size)
{
    const int*   x       = (const int*)  d_in[0];
    const int*   d_ids   = (const int*)  d_in[1];
    const int*   utt_len = (const int*)  d_in[2];
    const float* emb     = (const float*)d_in[3];
    const float* w_ih_f  = (const float*)d_in[4];
    const float* w_hh_f  = (const float*)d_in[5];
    const float* b_ih_f  = (const float*)d_in[6];
    const float* b_hh_f  = (const float*)d_in[7];
    const float* w_ih_b  = (const float*)d_in[8];
    const float* w_hh_b  = (const float*)d_in[9];
    const float* b_ih_b  = (const float*)d_in[10];
    const float* b_hh_b  = (const float*)d_in[11];
    const float* wq      = (const float*)d_in[12];
    const float* bq      = (const float*)d_in[13];
    const float* wk      = (const float*)d_in[14];
    const float* bk      = (const float*)d_in[15];
    const float* wv      = (const float*)d_in[16];
    const float* bv      = (const float*)d_in[17];
    const float* wo      = (const float*)d_in[18];
    const float* bo      = (const float*)d_in[19];
    const float* wl      = (const float*)d_in[20];
    const float* bl      = (const float*)d_in[21];
    float* out = (float*)d_out;

    prep_kernel<<<1, 1024>>>(d_ids, utt_len);
    transpose4_kernel<<<(4 * EE * EE) / 256, 256>>>(wq, wv, wo, wl);
    dim3 g1(NN * TT / BM, G2 / BN);
    xp_gemm_kernel<<<g1, 256>>>(x, emb, w_ih_f, w_ih_b, b_ih_f, b_ih_b);
    gru_kernel<<<512, 768>>>(w_hh_f, b_hh_f, w_hh_b, b_hh_b);
    attn_kernel<<<NN, 256>>>(bq, wk, bk, bv, bo, bl, out);
}